// round 16
// baseline (speedup 1.0000x reference)
#include <cuda_runtime.h>
#include <cuda_bf16.h>
#include <cstdint>

#define NUM_EXPERTS 16
#define Z_LOSS 1e-3f
#define ALPHA (1.0f / 1000.0f)

#define GRID 152                 // one block per SM on GB300
#define NTHREADS 288             // 256 consumers (8 warps) + 1 producer warp
#define CONSUMERS 256
#define NCWARPS 8                // consumer warps
#define NWARPS (NTHREADS / 32)   // 9
#define TILE_BYTES 8192
#define TILE_F4 (TILE_BYTES / 16)        // 512 float4 per tile
#define NSTAGES 5                        // 40KB ring (fits 48KB no-opt-in limit)
#define N_TILES 16384                    // 134217728 / 8192 exactly
#define SMEM_BYTES (NSTAGES * TILE_BYTES)

__device__ float g_partials[GRID];
__device__ int g_ticket = 0;   // reset by the last block each launch

__device__ __forceinline__ uint32_t smem_u32(const void* p) {
    uint32_t a;
    asm("{ .reg .u64 t; cvta.to.shared.u64 t, %1; cvt.u32.u64 %0, t; }"
        : "=r"(a) : "l"(p));
    return a;
}
__device__ __forceinline__ void mbar_init(uint32_t mba, uint32_t count) {
    asm volatile("mbarrier.init.shared.b64 [%0], %1;" :: "r"(mba), "r"(count) : "memory");
}
__device__ __forceinline__ void mbar_arrive(uint32_t mba) {
    asm volatile("mbarrier.arrive.release.cta.shared::cta.b64 _, [%0];" :: "r"(mba) : "memory");
}
__device__ __forceinline__ void bulk_load(uint32_t dst, const char* src, uint32_t mba) {
    asm volatile("mbarrier.arrive.expect_tx.shared::cta.b64 _, [%0], %1;"
                 :: "r"(mba), "r"((uint32_t)TILE_BYTES) : "memory");
    asm volatile("cp.async.bulk.shared::cta.global.mbarrier::complete_tx::bytes "
                 "[%0], [%1], %2, [%3];"
                 :: "r"(dst), "l"(src), "r"((uint32_t)TILE_BYTES), "r"(mba) : "memory");
}
__device__ __forceinline__ void mbar_wait(uint32_t mba, uint32_t parity) {
    asm volatile(
        "{\n\t"
        ".reg .pred P;\n\t"
        "WL_%=:\n\t"
        "mbarrier.try_wait.parity.acquire.cta.shared::cta.b64 P, [%0], %1, 0x989680;\n\t"
        "@P bra.uni WD_%=;\n\t"
        "bra.uni WL_%=;\n\t"
        "WD_%=:\n\t"
        "}"
        :: "r"(mba), "r"(parity) : "memory");
}

__global__ __launch_bounds__(NTHREADS, 1) void router_kernel(
    const char* __restrict__ x,
    const float* __restrict__ prototypes,
    const float* __restrict__ usage_ema,
    float* __restrict__ out, int out_size, float inv_n)
{
    extern __shared__ __align__(128) char smem_raw[];
    float4* smem = (float4*)smem_raw;
    __shared__ __align__(8) uint64_t full_mbar[NSTAGES];
    __shared__ __align__(8) uint64_t empty_mbar[NSTAGES];
    __shared__ float sdata[NWARPS];
    __shared__ float sh_xm;
    __shared__ bool is_last;

    const int tid = threadIdx.x;
    const int bid = blockIdx.x;
    // 16384 = 152*107 + 120 : blocks 0..119 get 108 tiles, rest 107
    const int my_tiles = (N_TILES / GRID) + (bid < (N_TILES % GRID) ? 1 : 0);

    if (tid == 0) {
        asm volatile("prefetch.global.L2 [%0];" :: "l"(prototypes));
        asm volatile("prefetch.global.L2 [%0];" :: "l"(usage_ema));
#pragma unroll
        for (int s = 0; s < NSTAGES; s++) {
            mbar_init(smem_u32(&full_mbar[s]), 1);
            mbar_init(smem_u32(&empty_mbar[s]), NCWARPS);   // one arrive per consumer warp
        }
    }
    __syncthreads();

    float s0 = 0.f, s1 = 0.f, s2 = 0.f, s3 = 0.f;

    if (tid >= CONSUMERS) {
        // ---- producer warp (only its leader does work) ----
        if (tid == CONSUMERS) {
            for (int t = 0; t < my_tiles; t++) {
                const int stage = t % NSTAGES;
                // producer parity starts flipped -> first NSTAGES waits pass immediately
                const uint32_t parity = (uint32_t)(((t / NSTAGES) + 1) & 1);
                mbar_wait(smem_u32(&empty_mbar[stage]), parity);
                const char* src = x + (size_t)(bid + t * GRID) * TILE_BYTES;
                bulk_load(smem_u32(smem_raw) + stage * TILE_BYTES, src,
                          smem_u32(&full_mbar[stage]));
            }
        }
    } else {
        // ---- 256 consumer threads, elected per-warp empty-arrives ----
        const bool lane0 = ((tid & 31) == 0);
        for (int t = 0; t < my_tiles; t++) {
            const int stage = t % NSTAGES;
            const uint32_t parity = (uint32_t)((t / NSTAGES) & 1);
            mbar_wait(smem_u32(&full_mbar[stage]), parity);

            const float4* tp = smem + stage * TILE_F4;
            float4 a = tp[tid];
            float4 b = tp[tid + CONSUMERS];
            s0 += a.x + b.x; s1 += a.y + b.y;
            s2 += a.z + b.z; s3 += a.w + b.w;

            __syncwarp();                 // all lanes of this warp done reading
            if (lane0)
                mbar_arrive(smem_u32(&empty_mbar[stage]));   // 1 arrive per warp
        }
    }
    float s = (s0 + s1) + (s2 + s3);

    // ---- block reduce over 9 warps (producer warp contributes 0) ----
#pragma unroll
    for (int off = 16; off > 0; off >>= 1)
        s += __shfl_down_sync(0xffffffffu, s, off);
    if ((tid & 31) == 0) sdata[tid >> 5] = s;
    __syncthreads();
    if (tid < 32) {
        float v = (tid < NWARPS) ? sdata[tid] : 0.f;
#pragma unroll
        for (int off = 16; off > 0; off >>= 1)
            v += __shfl_down_sync(0xffffffffu, v, off);
        if (tid == 0) {
            g_partials[bid] = v;
            __threadfence();
            int old = atomicAdd(&g_ticket, 1);
            is_last = (old == GRID - 1);
        }
    }
    __syncthreads();
    if (!is_last) return;

    // ---- tail (last block): reduce 152 partials ----
    float t = (tid < GRID) ? __ldcg(&g_partials[tid]) : 0.f;
#pragma unroll
    for (int off = 16; off > 0; off >>= 1)
        t += __shfl_down_sync(0xffffffffu, t, off);
    if ((tid & 31) == 0) sdata[tid >> 5] = t;

    // initialize every output element (d_out is poisoned with 0xAA)
    for (int i = tid; i < out_size; i += NTHREADS) out[i] = 0.0f;
    __syncthreads();

    if (tid == 0) {
        float tot = 0.f;
#pragma unroll
        for (int i = 0; i < NWARPS; i++) tot += sdata[i];
        sh_xm = tot * inv_n;
    }
    __syncthreads();

    // ---- warp-parallel epilogue: lane e owns expert e ----
    if (tid < 32) {
        const unsigned FULL = 0xffffffffu;
        const int lane = tid;
        const bool act = (lane < NUM_EXPERTS);
        const float xm = sh_xm;

        float sim = -3.4e38f;
        if (act) {
            float dd = prototypes[lane] - xm;
            sim = -dd * dd;
        }
        float mx = sim;
#pragma unroll
        for (int off = 16; off > 0; off >>= 1)
            mx = fmaxf(mx, __shfl_xor_sync(FULL, mx, off));

        float ex = act ? expf(sim - mx) : 0.f;
        float denom = ex;
#pragma unroll
        for (int off = 16; off > 0; off >>= 1)
            denom += __shfl_xor_sync(FULL, denom, off);
        float prob = act ? (ex / denom) : -1.f;

        // top-1, lowest-index tie-break (matches jax.lax.top_k)
        float bv = prob; int bi = lane;
#pragma unroll
        for (int off = 16; off > 0; off >>= 1) {
            float ov = __shfl_xor_sync(FULL, bv, off);
            int   oi = __shfl_xor_sync(FULL, bi, off);
            if (ov > bv || (ov == bv && oi < bi)) { bv = ov; bi = oi; }
        }
        const int i0 = bi;

        float v2 = (act && lane != i0) ? prob : -1.f;
        float bv2 = v2; int bi2 = lane;
#pragma unroll
        for (int off = 16; off > 0; off >>= 1) {
            float ov = __shfl_xor_sync(FULL, bv2, off);
            int   oi = __shfl_xor_sync(FULL, bi2, off);
            if (ov > bv2 || (ov == bv2 && oi < bi2)) { bv2 = ov; bi2 = oi; }
        }
        const int i1 = bi2;

        float mask = (lane == i0 || lane == i1) ? 1.f : 0.f;
        float ema = 0.f, sq = 0.f;
        if (act) {
            ema = (1.0f - ALPHA) * usage_ema[lane] + ALPHA * mask;
            float dd = ema - (1.0f / NUM_EXPERTS);
            sq = dd * dd;
        }
        float acc = sq;
#pragma unroll
        for (int off = 16; off > 0; off >>= 1)
            acc += __shfl_xor_sync(FULL, acc, off);

        // output layout: mask[16], probs[16], loss[1], ema[16], topk_idx[2]
        if (act) {
            out[lane] = mask;
            out[NUM_EXPERTS + lane] = prob;
            out[2 * NUM_EXPERTS + 1 + lane] = ema;
        }
        if (lane == 0) {
            out[2 * NUM_EXPERTS] = (acc / NUM_EXPERTS) * Z_LOSS;
            out[3 * NUM_EXPERTS + 1] = (float)i0;
            out[3 * NUM_EXPERTS + 2] = (float)i1;
            g_ticket = 0;   // reset for next graph replay
        }
    }
}

extern "C" void kernel_launch(void* const* d_in, const int* in_sizes, int n_in,
                              void* d_out, int out_size) {
    const char*  wm        = (const char*)d_in[0];
    const float* protos    = (const float*)d_in[1];
    const float* usage_ema = (const float*)d_in[2];
    float* out = (float*)d_out;

    const int n = in_sizes[0];  // 33554432
    router_kernel<<<GRID, NTHREADS, SMEM_BYTES>>>(wm, protos, usage_ema,
                                                  out, out_size, 1.0f / (float)n);
}

// round 17
// speedup vs baseline: 1.1600x; 1.1600x over previous
#include <cuda_runtime.h>
#include <cuda_bf16.h>
#include <cstdint>

#define NUM_EXPERTS 16
#define Z_LOSS 1e-3f
#define ALPHA (1.0f / 1000.0f)

#define R_BLOCKS 912             // 152 SMs * 6 blocks -> exactly one balanced wave
#define R_THREADS 256
#define N4_TOTAL 8388608u        // 4*4096*2048 floats / 4
#define R_STRIDE (R_BLOCKS * R_THREADS)   // 233472
#define FULL_ITERS 35u           // 35*233472 = 8171520; remainder 217088 predicated

__device__ float g_partials[R_BLOCKS];
__device__ int g_ticket = 0;   // reset to 0 by the last block each launch

__global__ __launch_bounds__(R_THREADS, 6) void router_kernel(
    const float4* __restrict__ x,
    const float* __restrict__ prototypes,
    const float* __restrict__ usage_ema,
    float* __restrict__ out, int out_size, float inv_n)
{
    __shared__ float sdata[R_THREADS / 32];
    __shared__ float sh_xm;
    __shared__ bool is_last;
    const int tid = threadIdx.x;

    // keep the tiny tail inputs L2-resident across the stream
    if (tid == 0) {
        asm volatile("prefetch.global.L2 [%0];" :: "l"(prototypes));
        asm volatile("prefetch.global.L2 [%0];" :: "l"(usage_ema));
    }

    // ---- phase 1: single balanced wave, coalesced evict-first stream ----
    const unsigned gid = blockIdx.x * R_THREADS + tid;

    float s0 = 0.f, s1 = 0.f, s2 = 0.f, s3 = 0.f;
#pragma unroll
    for (unsigned i = 0; i < FULL_ITERS; i++) {
        float4 v = __ldcs(&x[gid + i * R_STRIDE]);
        s0 += v.x; s1 += v.y; s2 += v.z; s3 += v.w;
    }
    {
        unsigned idx = gid + FULL_ITERS * R_STRIDE;
        if (idx < N4_TOTAL) {
            float4 v = __ldcs(&x[idx]);
            s0 += v.x; s1 += v.y; s2 += v.z; s3 += v.w;
        }
    }
    float s = (s0 + s1) + (s2 + s3);

#pragma unroll
    for (int off = 16; off > 0; off >>= 1)
        s += __shfl_down_sync(0xffffffffu, s, off);

    if ((tid & 31) == 0) sdata[tid >> 5] = s;
    __syncthreads();
    if (tid < 32) {
        float v = (tid < R_THREADS / 32) ? sdata[tid] : 0.f;
#pragma unroll
        for (int off = 4; off > 0; off >>= 1)
            v += __shfl_down_sync(0xffffffffu, v, off);
        if (tid == 0) {
            g_partials[blockIdx.x] = v;
            __threadfence();
            int old = atomicAdd(&g_ticket, 1);
            is_last = (old == R_BLOCKS - 1);
        }
    }
    __syncthreads();
    if (!is_last) return;

    // ---- phase 2 (last block only): reduce 912 partials ----
    float t = 0.f;
#pragma unroll
    for (int i = 0; i < (R_BLOCKS + R_THREADS - 1) / R_THREADS; i++) {
        int idx = tid + i * R_THREADS;
        if (idx < R_BLOCKS) t += __ldcg(&g_partials[idx]);
    }
#pragma unroll
    for (int off = 16; off > 0; off >>= 1)
        t += __shfl_down_sync(0xffffffffu, t, off);
    if ((tid & 31) == 0) sdata[tid >> 5] = t;

    // initialize every output element (d_out is poisoned with 0xAA)
    for (int i = tid; i < out_size; i += R_THREADS) out[i] = 0.0f;
    __syncthreads();

    if (tid == 0) {
        float tot = 0.f;
#pragma unroll
        for (int i = 0; i < R_THREADS / 32; i++) tot += sdata[i];
        sh_xm = tot * inv_n;
    }
    __syncthreads();

    // ---- warp-parallel epilogue: lane e owns expert e (lanes 16-31 inert) ----
    if (tid < 32) {
        const unsigned FULL = 0xffffffffu;
        const int lane = tid;
        const bool act = (lane < NUM_EXPERTS);
        const float xm = sh_xm;

        float sim = -3.4e38f;
        if (act) {
            float dd = prototypes[lane] - xm;
            sim = -dd * dd;
        }
        float mx = sim;
#pragma unroll
        for (int off = 16; off > 0; off >>= 1)
            mx = fmaxf(mx, __shfl_xor_sync(FULL, mx, off));

        float ex = act ? expf(sim - mx) : 0.f;
        float denom = ex;
#pragma unroll
        for (int off = 16; off > 0; off >>= 1)
            denom += __shfl_xor_sync(FULL, denom, off);
        float prob = act ? (ex / denom) : -1.f;

        // top-1, lowest-index tie-break (matches jax.lax.top_k)
        float bv = prob; int bi = lane;
#pragma unroll
        for (int off = 16; off > 0; off >>= 1) {
            float ov = __shfl_xor_sync(FULL, bv, off);
            int   oi = __shfl_xor_sync(FULL, bi, off);
            if (ov > bv || (ov == bv && oi < bi)) { bv = ov; bi = oi; }
        }
        const int i0 = bi;

        float v2 = (act && lane != i0) ? prob : -1.f;
        float bv2 = v2; int bi2 = lane;
#pragma unroll
        for (int off = 16; off > 0; off >>= 1) {
            float ov = __shfl_xor_sync(FULL, bv2, off);
            int   oi = __shfl_xor_sync(FULL, bi2, off);
            if (ov > bv2 || (ov == bv2 && oi < bi2)) { bv2 = ov; bi2 = oi; }
        }
        const int i1 = bi2;

        float mask = (lane == i0 || lane == i1) ? 1.f : 0.f;
        float ema = 0.f, sq = 0.f;
        if (act) {
            ema = (1.0f - ALPHA) * usage_ema[lane] + ALPHA * mask;
            float dd = ema - (1.0f / NUM_EXPERTS);
            sq = dd * dd;
        }
        float acc = sq;
#pragma unroll
        for (int off = 16; off > 0; off >>= 1)
            acc += __shfl_xor_sync(FULL, acc, off);

        // output layout: mask[16], probs[16], loss[1], ema[16], topk_idx[2]
        if (act) {
            out[lane] = mask;
            out[NUM_EXPERTS + lane] = prob;
            out[2 * NUM_EXPERTS + 1 + lane] = ema;
        }
        if (lane == 0) {
            out[2 * NUM_EXPERTS] = (acc / NUM_EXPERTS) * Z_LOSS;
            out[3 * NUM_EXPERTS + 1] = (float)i0;
            out[3 * NUM_EXPERTS + 2] = (float)i1;
            g_ticket = 0;   // reset for next graph replay
        }
    }
}

extern "C" void kernel_launch(void* const* d_in, const int* in_sizes, int n_in,
                              void* d_out, int out_size) {
    const float* wm        = (const float*)d_in[0];
    const float* protos    = (const float*)d_in[1];
    const float* usage_ema = (const float*)d_in[2];
    float* out = (float*)d_out;

    const int n = in_sizes[0];  // 33554432
    router_kernel<<<R_BLOCKS, R_THREADS>>>((const float4*)wm, protos, usage_ema,
                                           out, out_size, 1.0f / (float)n);
}